// round 7
// baseline (speedup 1.0000x reference)
#include <cuda_runtime.h>

// Fused sum-over-seq + concat:  out[b,i,d] = sum_l x_i[b,l,d]
// 8 inputs x_i : [512, L_i, 128] fp32, L_i = 64*(i+1); out : [512, 8, 128] fp32.
//
// R6: pair-balanced + high-occupancy + atomic-free + single node.
//   Pair input p with input 7-p: every pair totals 576 rows -> all 2048
//   (batch, pair) CTA-tasks are byte-identical (288KB read each).
//   CTA = 128 threads, 4 warps; warp w sums rows {w, w+4, ...} of both inputs
//   (144 rows each), lane c owns float4 column c. smem reduce: warp 0 writes
//   output row A, warp 1 writes output row B.
//   2048 CTAs @ 14/SM -> single wave, 56 warps/SM feeding the memory system.

#define NUM_IN 8
#define BATCH 512
#define DVEC 32      // 128 floats = 32 float4 per row

struct Args {
    const float4* in[NUM_IN];
    int len[NUM_IN];
};

// Sum rows {w, w+4, w+8, ...} of an [L, 128] fp32 matrix, lane's float4 column.
// L multiple of 64 -> per-warp row count L/4 is a multiple of 16: unroll 4 clean.
__device__ __forceinline__ float4 sum_rows_striped(const float4* __restrict__ base,
                                                   int L, int w, int lane) {
    const float4* __restrict__ p = base + (size_t)w * DVEC + lane;
    float4 acc = make_float4(0.f, 0.f, 0.f, 0.f);
    for (int l = w; l < L; l += 16) {
        const float4 v0 = __ldcs(p);
        const float4 v1 = __ldcs(p + 4 * DVEC);
        const float4 v2 = __ldcs(p + 8 * DVEC);
        const float4 v3 = __ldcs(p + 12 * DVEC);
        p += 16 * DVEC;
        acc.x += (v0.x + v1.x) + (v2.x + v3.x);
        acc.y += (v0.y + v1.y) + (v2.y + v3.y);
        acc.z += (v0.z + v1.z) + (v2.z + v3.z);
        acc.w += (v0.w + v1.w) + (v2.w + v3.w);
    }
    return acc;
}

__global__ __launch_bounds__(128, 14)
void sum_cat_pair_occ_kernel(Args args, float4* __restrict__ out) {
    const int lane = threadIdx.x & 31;
    const int w    = threadIdx.x >> 5;

    const int task = blockIdx.x;        // [0, 2048)
    const int p = task >> 9;            // pair index 0..3
    const int b = task & (BATCH - 1);   // batch element

    const int iA = p;
    const int iB = (NUM_IN - 1) - p;
    const int LA = args.len[iA];
    const int LB = args.len[iB];

    const float4* baseA = args.in[iA] + (size_t)b * (size_t)LA * DVEC;
    const float4* baseB = args.in[iB] + (size_t)b * (size_t)LB * DVEC;

    const float4 accA = sum_rows_striped(baseA, LA, w, lane);
    const float4 accB = sum_rows_striped(baseB, LB, w, lane);

    __shared__ float4 sm[2][4][DVEC];   // [input][warp][lane] = 4KB
    sm[0][w][lane] = accA;
    sm[1][w][lane] = accB;
    __syncthreads();

    if (w < 2) {                        // warp 0 -> output A, warp 1 -> output B
        const float4 a0 = sm[w][0][lane];
        const float4 a1 = sm[w][1][lane];
        const float4 a2 = sm[w][2][lane];
        const float4 a3 = sm[w][3][lane];
        float4 r;
        r.x = (a0.x + a1.x) + (a2.x + a3.x);
        r.y = (a0.y + a1.y) + (a2.y + a3.y);
        r.z = (a0.z + a1.z) + (a2.z + a3.z);
        r.w = (a0.w + a1.w) + (a2.w + a3.w);
        const int i = (w == 0) ? iA : iB;
        out[((size_t)b * NUM_IN + i) * DVEC + lane] = r;
    }
}

extern "C" void kernel_launch(void* const* d_in, const int* in_sizes, int n_in,
                              void* d_out, int out_size) {
    Args args;
    for (int i = 0; i < NUM_IN; ++i) {
        args.in[i]  = (const float4*)d_in[i];
        args.len[i] = in_sizes[i] / (BATCH * 128);   // = L_i
    }
    // 2048 identical CTA-tasks, 14/SM -> single wave on 148 SMs.
    sum_cat_pair_occ_kernel<<<(NUM_IN / 2) * BATCH, 128>>>(args, (float4*)d_out);
}

// round 8
// speedup vs baseline: 1.0003x; 1.0003x over previous
#include <cuda_runtime.h>

// Fused sum-over-seq + concat:  out[b,i,d] = sum_l x_i[b,l,d]
// 8 inputs x_i : [512, L_i, 128] fp32, L_i = 64*(i+1); out : [512, 8, 128] fp32.
//
// R7: pair-balanced halves — 16-deep contiguous streaming (R4's proven 93%
// steady-state loop) + fine task granularity to kill the 15.6% wave tail.
//   Pair p <-> 7-p totals 576 rows. Split into two 288-row half-tasks:
//     warp 0: all of A (LA rows) + first 288-LA rows of B
//     warp 1: last 288 rows of B
//   CTA = 2 warps = one (b, pair); B-partials combined via 1KB smem.
//   2048 uniform CTAs, ~12/SM resident -> 1.15 waves, ~1.2% imbalance.

#define NUM_IN 8
#define BATCH 512
#define DVEC 32      // 128 floats = 32 float4 per row
#define UNROLL 16

struct Args {
    const float4* in[NUM_IN];
    int len[NUM_IN];
};

// Sum nrows consecutive rows (nrows multiple of 16), lane's float4 column.
__device__ __forceinline__ float4 seg_sum(const float4* __restrict__ base,
                                          int nrows, int lane, float4 acc) {
    const float4* __restrict__ p = base + lane;
    for (int l = 0; l < nrows; l += UNROLL) {
        float4 v[UNROLL];
        #pragma unroll
        for (int u = 0; u < UNROLL; ++u)
            v[u] = __ldcs(p + (size_t)(l + u) * DVEC);   // read-once stream
        #pragma unroll
        for (int u = 0; u < UNROLL; ++u) {
            acc.x += v[u].x; acc.y += v[u].y;
            acc.z += v[u].z; acc.w += v[u].w;
        }
    }
    return acc;
}

__global__ __launch_bounds__(64, 12)
void sum_cat_half_kernel(Args args, float4* __restrict__ out) {
    const int lane = threadIdx.x & 31;
    const int w    = threadIdx.x >> 5;     // 0 or 1

    const int task = blockIdx.x;           // [0, 2048)
    const int p = task >> 9;               // pair 0..3
    const int b = task & (BATCH - 1);

    const int iA = p;
    const int iB = (NUM_IN - 1) - p;
    const int LA = args.len[iA];           // 64..256
    const int LB = args.len[iB];           // 320..512

    const float4* baseA = args.in[iA] + (size_t)b * (size_t)LA * DVEC;
    const float4* baseB = args.in[iB] + (size_t)b * (size_t)LB * DVEC;

    const int splitB = 288 - LA;           // rows of B in warp 0 (mult of 32)

    float4 accA = make_float4(0.f, 0.f, 0.f, 0.f);
    float4 accB = make_float4(0.f, 0.f, 0.f, 0.f);

    if (w == 0) {
        accA = seg_sum(baseA, LA, lane, accA);                    // all of A
        accB = seg_sum(baseB, splitB, lane, accB);                // B[0, splitB)
    } else {
        accB = seg_sum(baseB + (size_t)splitB * DVEC, 288, lane, accB); // B rest
    }

    __shared__ float4 smB[2][DVEC];        // 1KB
    smB[w][lane] = accB;
    __syncthreads();

    if (w == 0) {
        // out[b, i, :] -> float4 index (b*8 + i)*32 + lane
        out[((size_t)b * NUM_IN + iA) * DVEC + lane] = accA;
    } else {
        const float4 b0 = smB[0][lane];
        const float4 b1 = smB[1][lane];
        float4 r;
        r.x = b0.x + b1.x; r.y = b0.y + b1.y;
        r.z = b0.z + b1.z; r.w = b0.w + b1.w;
        out[((size_t)b * NUM_IN + iB) * DVEC + lane] = r;
    }
}

extern "C" void kernel_launch(void* const* d_in, const int* in_sizes, int n_in,
                              void* d_out, int out_size) {
    Args args;
    for (int i = 0; i < NUM_IN; ++i) {
        args.in[i]  = (const float4*)d_in[i];
        args.len[i] = in_sizes[i] / (BATCH * 128);   // = L_i
    }
    // 2048 uniform (b, pair) tasks, 2 warps each.
    sum_cat_half_kernel<<<(NUM_IN / 2) * BATCH, 64>>>(args, (float4*)d_out);
}

// round 13
// speedup vs baseline: 1.0446x; 1.0442x over previous
#include <cuda_runtime.h>

// Fused sum-over-seq + concat:  out[b,i,d] = sum_l x_i[b,l,d]
// 8 inputs x_i : [512, L_i, 128] fp32, L_i = 64*(i+1); out : [512, 8, 128] fp32.
//
// R12 (= R8 resubmitted after infra failure) = R4 (best: 93.0us) with the
// wave tail fixed.
//   R4: 512 CTAs x 4 warps -> 68 SMs get 4 CTAs, 80 get 3 -> ~15% tail on
//   68 SMs. Here the SAME 576-row pair warp-task (L_p + L_{7-p} = 576) becomes
//   its own 32-thread CTA: grid = 2048 identical CTAs -> 14 vs 13 CTAs/SM =
//   1.2% imbalance, single wave, same ~14 warps/SM, no smem, no syncs.
//   Inner loop unchanged: 16 outstanding LDG.128 per thread, evict-first.

#define NUM_IN 8
#define BATCH 512
#define DVEC 32      // 128 floats = 32 float4 per row
#define UNROLL 16    // rows in flight per thread (all L_i multiples of 64)

struct Args {
    const float4* in[NUM_IN];
    int len[NUM_IN];
};

__device__ __forceinline__ float4 sum_rows(const float4* __restrict__ base,
                                           int L, int lane) {
    const float4* __restrict__ p = base + lane;
    float4 acc = make_float4(0.f, 0.f, 0.f, 0.f);
    for (int l = 0; l < L; l += UNROLL) {
        float4 v[UNROLL];
        #pragma unroll
        for (int u = 0; u < UNROLL; ++u)
            v[u] = __ldcs(p + (size_t)(l + u) * DVEC);   // read-once: evict-first
        #pragma unroll
        for (int u = 0; u < UNROLL; ++u) {
            acc.x += v[u].x; acc.y += v[u].y;
            acc.z += v[u].z; acc.w += v[u].w;
        }
    }
    return acc;
}

__global__ __launch_bounds__(32, 16)
void sum_cat_pair1w_kernel(Args args, float4* __restrict__ out) {
    const int lane = threadIdx.x;          // 32-thread CTA = one warp-task
    const int W    = blockIdx.x;           // task id in [0, 2048)

    const int p = W >> 9;                  // pair index 0..3
    const int b = W & (BATCH - 1);         // batch element

    const int iA = p;                      // shorter input of the pair
    const int iB = (NUM_IN - 1) - p;

    const int LA = args.len[iA];
    const int LB = args.len[iB];

    const float4* baseA = args.in[iA] + (size_t)b * (size_t)LA * DVEC;
    const float4* baseB = args.in[iB] + (size_t)b * (size_t)LB * DVEC;

    const float4 accA = sum_rows(baseA, LA, lane);
    const float4 accB = sum_rows(baseB, LB, lane);

    // out[b, i, :] -> float4 index (b*8 + i)*32 + lane
    out[((size_t)b * NUM_IN + iA) * DVEC + lane] = accA;
    out[((size_t)b * NUM_IN + iB) * DVEC + lane] = accB;
}

extern "C" void kernel_launch(void* const* d_in, const int* in_sizes, int n_in,
                              void* d_out, int out_size) {
    Args args;
    for (int i = 0; i < NUM_IN; ++i) {
        args.in[i]  = (const float4*)d_in[i];
        args.len[i] = in_sizes[i] / (BATCH * 128);   // = L_i
    }
    // 2048 identical single-warp CTA-tasks -> single wave, ~14 per SM.
    sum_cat_pair1w_kernel<<<(NUM_IN / 2) * BATCH, 32, 0, (cudaStream_t)0>>>(
        args, (float4*)d_out);
}